// round 12
// baseline (speedup 1.0000x reference)
#include <cuda_runtime.h>
#include <cuda_fp16.h>
#include <cstdint>

typedef unsigned long long ull;

// ---------------- scratch (static device allocations; no cudaMalloc) ----------------
__device__ __half g_xw1h[268435456];  // [T=512][B=1024][n=512] fp16  (512 MiB)

// preconverted weights (fp16) + combined biases (fp32)
// Gate-column mapping (layer 1): n = wq*64 + s, wq = j/16:
//   s = 2*(j%16) + q          q in {0,1}  (i,f pairs -> tiles 0..3 of warp)
//   s = 32 + 2*(j%16) + q-2   q in {2,3}  (g,o pairs -> tiles 4..7)
// Layer 2: 32-col blocks, 8 units each, analogous.
__device__ __half g_w1[512 * 112];    // W1_ih n-major: [n][k], k padded 100->112
__device__ __half g_w2[256 * 128];    // W2_ih n-major: [n][k=128]
__device__ __half g_w1hh[65536];      // W1_hh n-major: [n=512][k=128]
__device__ __half g_w2hh[16384];      // W2_hh n-major: [n=256][k=64]
__device__ float  g_b1[512];
__device__ float  g_b2[256];

// ---------------- helpers ----------------
__device__ __forceinline__ float sigf(float x){ return 1.f / (1.f + __expf(-x)); }
__device__ __forceinline__ float tanha(float x){
    float y; asm("tanh.approx.f32 %0, %1;" : "=f"(y) : "f"(x)); return y;
}
__device__ __forceinline__ float siga(float x){ return fmaf(0.5f, tanha(0.5f * x), 0.5f); }

__device__ __forceinline__ uint32_t smem_u32(const void* p){
    return (uint32_t)__cvta_generic_to_shared(p);
}

__device__ __forceinline__ void mma16816(float& c0, float& c1, float& c2, float& c3,
                                         uint32_t a0, uint32_t a1, uint32_t a2, uint32_t a3,
                                         uint32_t b0, uint32_t b1){
    asm("mma.sync.aligned.m16n8k16.row.col.f32.f16.f16.f32 "
        "{%0,%1,%2,%3}, {%4,%5,%6,%7}, {%8,%9}, {%0,%1,%2,%3};"
        : "+f"(c0), "+f"(c1), "+f"(c2), "+f"(c3)
        : "r"(a0), "r"(a1), "r"(a2), "r"(a3), "r"(b0), "r"(b1));
}

__device__ __forceinline__ void ldsm_x4(uint32_t& r0, uint32_t& r1, uint32_t& r2, uint32_t& r3,
                                        uint32_t addr){
    asm("ldmatrix.sync.aligned.m8n8.x4.shared.b16 {%0,%1,%2,%3}, [%4];"
        : "=r"(r0), "=r"(r1), "=r"(r2), "=r"(r3) : "r"(addr));
}

// gate mapping helpers (prep only) — layer1: 64-col blocks, layer2: 32-col blocks
__device__ __forceinline__ void n_to_gj1(int n, int& g, int& j){
    int wq = n >> 6, s = n & 63;
    int q;
    if (s < 32){ j = wq * 16 + (s >> 1); q = s & 1; }
    else        { int s2 = s - 32; j = wq * 16 + (s2 >> 1); q = 2 + (s2 & 1); }
    g = q * 128 + j;
}
__device__ __forceinline__ void n_to_gj2(int n, int& g, int& j){
    int wq = n >> 5, s = n & 31;
    int q;
    if (s < 16){ j = wq * 8 + (s >> 1); q = s & 1; }
    else        { int s2 = s - 16; j = wq * 8 + (s2 >> 1); q = 2 + (s2 & 1); }
    g = q * 64 + j;
}

// =====================================================================
// PREP: one-shot weight conversion with gate-pair column mapping
// =====================================================================
__global__ void __launch_bounds__(256) prep_kernel(
    const float* __restrict__ W1_ih, const float* __restrict__ W1_hh,
    const float* __restrict__ b1_ih, const float* __restrict__ b1_hh,
    const float* __restrict__ W2_ih, const float* __restrict__ W2_hh,
    const float* __restrict__ b2_ih, const float* __restrict__ b2_hh)
{
    const int tid = blockIdx.x * blockDim.x + threadIdx.x;
    const int stride = gridDim.x * blockDim.x;
    for (int i = tid; i < 512 * 112; i += stride){
        int n = i / 112, k = i - n * 112;
        int g, j; n_to_gj1(n, g, j);
        g_w1[i] = __float2half(k < 100 ? W1_ih[g * 100 + k] : 0.f);
    }
    for (int i = tid; i < 256 * 128; i += stride){
        int n = i >> 7, k = i & 127;
        int g, j; n_to_gj2(n, g, j);
        g_w2[i] = __float2half(W2_ih[g * 128 + k]);
    }
    for (int i = tid; i < 65536; i += stride){
        int n = i >> 7, k = i & 127;
        int g, j; n_to_gj1(n, g, j);
        g_w1hh[i] = __float2half(W1_hh[g * 128 + k]);
    }
    for (int i = tid; i < 16384; i += stride){
        int n = i >> 6, k = i & 63;
        int g, j; n_to_gj2(n, g, j);
        g_w2hh[i] = __float2half(W2_hh[g * 64 + k]);
    }
    for (int i = tid; i < 512; i += stride){
        int g, j; n_to_gj1(i, g, j);
        g_b1[i] = b1_ih[g] + b1_hh[g];
    }
    for (int i = tid; i < 256; i += stride){
        int g, j; n_to_gj2(i, g, j);
        g_b2[i] = b2_ih[g] + b2_hh[g];
    }
}

// =====================================================================
// GEMM1 (tensor core, unchanged)
// =====================================================================
__global__ void __launch_bounds__(256) gemm1_tc(const float* __restrict__ X)
{
    extern __shared__ __half sm[];
    __half* sA = sm;               // [128][120]
    __half* sB = sm + 128 * 120;   // [128][120] n-major
    const int tid = threadIdx.x;
    const int cb = blockIdx.x;
    const int rb = blockIdx.y;
    const int r0 = rb * 128;
    const int n0c = cb * 128;

    const float4* X4 = (const float4*)(X + (size_t)r0 * 100);
    for (int idx = tid; idx < 3200; idx += 256){
        int row = idx / 25, c4 = idx - row * 25;
        float4 v = X4[row * 25 + c4];
        __half2 h0 = __floats2half2_rn(v.x, v.y);
        __half2 h1 = __floats2half2_rn(v.z, v.w);
        ull packed = ((ull)(*(uint32_t*)&h1) << 32) | (*(uint32_t*)&h0);
        *(ull*)(sA + row * 120 + c4 * 4) = packed;
    }
    for (int idx = tid; idx < 768; idx += 256){
        int row = idx / 6, e = (idx - row * 6) * 2;
        *(uint32_t*)(sA + row * 120 + 100 + e) = 0u;
    }
    for (int idx = tid; idx < 1792; idx += 256){
        int nn = idx / 14, c8 = (idx - nn * 14) * 8;
        *(int4*)(sB + nn * 120 + c8) = *(const int4*)(g_w1 + (size_t)(n0c + nn) * 112 + c8);
    }
    __syncthreads();

    const int w = tid >> 5, lane = tid & 31;
    const int wm = w >> 2, wn = w & 3;
    const int m0w = wm * 64, n0w = wn * 32;
    const int gp = lane >> 2, tig = lane & 3;

    float acc[4][4][4];
    #pragma unroll
    for (int mt = 0; mt < 4; mt++)
        #pragma unroll
        for (int nt = 0; nt < 4; nt++){
            acc[mt][nt][0]=0.f; acc[mt][nt][1]=0.f; acc[mt][nt][2]=0.f; acc[mt][nt][3]=0.f;
        }

    float2 bias[4];
    #pragma unroll
    for (int nt = 0; nt < 4; nt++)
        bias[nt] = *(const float2*)(g_b1 + n0c + n0w + nt * 8 + 2 * tig);

    #pragma unroll
    for (int kt = 0; kt < 7; kt++){
        const int k0 = kt * 16;
        uint32_t af[4][4];
        #pragma unroll
        for (int mt = 0; mt < 4; mt++){
            const __half* ap = sA + (m0w + mt * 16 + gp) * 120 + k0 + 2 * tig;
            af[mt][0] = *(const uint32_t*)ap;
            af[mt][1] = *(const uint32_t*)(ap + 8 * 120);
            af[mt][2] = *(const uint32_t*)(ap + 8);
            af[mt][3] = *(const uint32_t*)(ap + 8 * 120 + 8);
        }
        #pragma unroll
        for (int nt = 0; nt < 4; nt++){
            const __half* bp = sB + (n0w + nt * 8 + gp) * 120 + k0 + 2 * tig;
            uint32_t b0 = *(const uint32_t*)bp;
            uint32_t b1 = *(const uint32_t*)(bp + 8);
            #pragma unroll
            for (int mt = 0; mt < 4; mt++)
                mma16816(acc[mt][nt][0], acc[mt][nt][1], acc[mt][nt][2], acc[mt][nt][3],
                         af[mt][0], af[mt][1], af[mt][2], af[mt][3], b0, b1);
        }
    }

    __syncthreads();
    __half* stg = sm;   // [128][136]
    #pragma unroll
    for (int mt = 0; mt < 4; mt++){
        int ra = m0w + mt * 16 + gp;
        #pragma unroll
        for (int nt = 0; nt < 4; nt++){
            int nl = n0w + nt * 8 + 2 * tig;
            __half2 v0 = __floats2half2_rn(acc[mt][nt][0] + bias[nt].x, acc[mt][nt][1] + bias[nt].y);
            __half2 v1 = __floats2half2_rn(acc[mt][nt][2] + bias[nt].x, acc[mt][nt][3] + bias[nt].y);
            *(__half2*)(stg + ra * 136 + nl) = v0;
            *(__half2*)(stg + (ra + 8) * 136 + nl) = v1;
        }
    }
    __syncthreads();
    #pragma unroll
    for (int i = 0; i < 8; i++){
        int idx = tid + i * 256;
        int row = idx >> 4, col8 = (idx & 15) * 8;
        int r = r0 + row;
        size_t orow = (size_t)(r & 511) * 1024 + (r >> 9);
        *(int4*)(g_xw1h + orow * 512 + n0c + col8) = *(const int4*)(stg + row * 136 + col8);
    }
}

// =====================================================================
// FUSED v2 (software-pipelined): at iteration t,
//   rec1: h1[t] from h1[t-1], xw1[t]
//   proj: p = h1[t-1] @ W2ih   (A-frags SHARED with rec1, reg-resident)
//   rec2: h2[t-1] from h2[t-2] and p  (skipped at t=0)
// ONE __syncthreads per iteration. Tail iteration produces h2[511].
// 128 CTAs x 8 batch rows, 8 warps.
// =====================================================================
__global__ void __launch_bounds__(256, 1) fused_kernel(
    const float* __restrict__ fc1w, const float* __restrict__ fc1b,
    const float* __restrict__ fc2w, const float* __restrict__ fc2b,
    float* __restrict__ out)
{
    extern __shared__ __half smf[];
    __half* sW1  = smf;                    // [512][136]
    __half* sW2i = smf + 512 * 136;        // [256][136]
    __half* sH1  = smf + 768 * 136;        // [2][8][136]
    __half* sH2  = sH1 + 2 * 8 * 136;      // [2][8][72]

    const int tid  = threadIdx.x;
    const int w    = tid >> 5;
    const int lane = tid & 31;
    const int gp   = lane >> 2;
    const int tig  = lane & 3;
    const int b0   = blockIdx.x * 8;

    // ---- init 1: stage W2hh [256][72] into sW1 region, build reg fragments ----
    for (int idx = tid; idx < 2048; idx += 256){
        int nn = idx >> 3, c8 = (idx & 7) * 8;
        *(int4*)(sW1 + nn * 72 + c8) = *(const int4*)(g_w2hh + nn * 64 + c8);
    }
    __syncthreads();

    uint32_t fhh[4][2][4];   // [k2t][pair][r0..r3]
    {
        int rowo = (lane & 7) + ((lane & 16) ? 8 : 0);
        int kcol = ((lane >> 3) & 1) * 8;
        uint32_t base = smem_u32(sW1);
        #pragma unroll
        for (int p = 0; p < 2; p++){
            uint32_t addr = base + (uint32_t)(((w * 32 + p * 16 + rowo) * 72 + kcol) * 2);
            #pragma unroll
            for (int k2t = 0; k2t < 4; k2t++)
                ldsm_x4(fhh[k2t][p][0], fhh[k2t][p][1], fhh[k2t][p][2], fhh[k2t][p][3],
                        addr + (uint32_t)(k2t * 32));
        }
    }
    __syncthreads();

    // ---- init 2: load W1hh, W2ih; zero h buffers ----
    for (int idx = tid; idx < 8192; idx += 256){
        int nn = idx >> 4, c8 = (idx & 15) * 8;
        *(int4*)(sW1 + nn * 136 + c8) = *(const int4*)(g_w1hh + nn * 128 + c8);
    }
    for (int idx = tid; idx < 4096; idx += 256){
        int nn = idx >> 4, c8 = (idx & 15) * 8;
        *(int4*)(sW2i + nn * 136 + c8) = *(const int4*)(g_w2 + nn * 128 + c8);
    }
    for (int i = tid; i < 1088; i += 256) ((uint32_t*)sH1)[i] = 0u;
    for (int i = tid; i < 576; i += 256)  ((uint32_t*)sH2)[i] = 0u;
    __syncthreads();

    // ldmatrix bases
    uint32_t bb1[4], bb2[2];
    {
        int rowo = (lane & 7) + ((lane & 16) ? 8 : 0);
        int kcol = ((lane >> 3) & 1) * 8;
        uint32_t w1base = smem_u32(sW1);
        #pragma unroll
        for (int ntp = 0; ntp < 4; ntp++)
            bb1[ntp] = w1base + (uint32_t)(((w * 64 + ntp * 16 + rowo) * 136 + kcol) * 2);
        uint32_t w2base = smem_u32(sW2i);
        #pragma unroll
        for (int ntp = 0; ntp < 2; ntp++)
            bb2[ntp] = w2base + (uint32_t)(((w * 32 + ntp * 16 + rowo) * 136 + kcol) * 2);
    }

    float cst1[4] = {0.f, 0.f, 0.f, 0.f};
    float cst2[2] = {0.f, 0.f};
    const uint32_t zero = 0u;
    const int cA     = w * 64 + 2 * tig;
    const int ubase1 = w * 16 + tig;
    const int ubase2 = w * 8 + tig;

    float2 bias2[4];
    #pragma unroll
    for (int nt = 0; nt < 4; nt++)
        bias2[nt] = *(const float2*)(g_b2 + w * 32 + nt * 8 + 2 * tig);

    // preload xw1 for t=0
    uint32_t xcur[8], xnxt[8];
    {
        const __half* xb = g_xw1h + ((size_t)b0 + gp) * 512 + cA;
        #pragma unroll
        for (int nt = 0; nt < 8; nt++) xcur[nt] = *(const uint32_t*)(xb + nt * 8);
    }

    for (int t = 0; t < 512; t++){
        const __half* hr1 = sH1 + (1 - (t & 1)) * 8 * 136;   // h1[t-1]
        __half*       hw1 = sH1 + (t & 1) * 8 * 136;         // h1[t]
        const __half* hr2 = sH2 + (t & 1) * 8 * 72;          // h2[t-2]
        __half*       hw2 = sH2 + (1 - (t & 1)) * 8 * 72;    // h2[t-1]

        // prefetch xw1 for t+1
        {
            int tn = (t < 511) ? t + 1 : t;
            const __half* xb = g_xw1h + ((size_t)tn * 1024 + b0 + gp) * 512 + cA;
            #pragma unroll
            for (int nt = 0; nt < 8; nt++) xnxt[nt] = *(const uint32_t*)(xb + nt * 8);
        }

        // ---- merged MMA stream ----
        float acc[8][4];
        #pragma unroll
        for (int nt = 0; nt < 8; nt++){
            acc[nt][0]=0.f; acc[nt][1]=0.f; acc[nt][2]=0.f; acc[nt][3]=0.f;
        }
        float accp[4][4];
        #pragma unroll
        for (int nt = 0; nt < 4; nt++){
            accp[nt][0]=0.f; accp[nt][1]=0.f; accp[nt][2]=0.f; accp[nt][3]=0.f;
        }
        float acc2h[4][4];
        #pragma unroll
        for (int nt = 0; nt < 4; nt++){
            acc2h[nt][0]=0.f; acc2h[nt][1]=0.f; acc2h[nt][2]=0.f; acc2h[nt][3]=0.f;
        }

        // rec2hh MMAs on h2[t-2]
        #pragma unroll
        for (int k2t = 0; k2t < 4; k2t++){
            const int k0 = k2t * 16;
            const __half* ap = hr2 + gp * 72 + k0 + 2 * tig;
            uint32_t a0 = *(const uint32_t*)ap;
            uint32_t a2 = *(const uint32_t*)(ap + 8);
            #pragma unroll
            for (int p = 0; p < 2; p++){
                mma16816(acc2h[2*p][0],   acc2h[2*p][1],   acc2h[2*p][2],   acc2h[2*p][3],
                         a0, zero, a2, zero, fhh[k2t][p][0], fhh[k2t][p][1]);
                mma16816(acc2h[2*p+1][0], acc2h[2*p+1][1], acc2h[2*p+1][2], acc2h[2*p+1][3],
                         a0, zero, a2, zero, fhh[k2t][p][2], fhh[k2t][p][3]);
            }
        }

        // rec1 + proj MMAs share A-frags (h1[t-1])
        #pragma unroll
        for (int kt = 0; kt < 8; kt++){
            const int k0 = kt * 16;
            const __half* ap = hr1 + gp * 136 + k0 + 2 * tig;
            uint32_t a0 = *(const uint32_t*)ap;
            uint32_t a2 = *(const uint32_t*)(ap + 8);
            #pragma unroll
            for (int ntp = 0; ntp < 4; ntp++){
                uint32_t r0, r1, r2, r3;
                ldsm_x4(r0, r1, r2, r3, bb1[ntp] + (uint32_t)(k0 * 2));
                mma16816(acc[2*ntp][0],   acc[2*ntp][1],   acc[2*ntp][2],   acc[2*ntp][3],
                         a0, zero, a2, zero, r0, r1);
                mma16816(acc[2*ntp+1][0], acc[2*ntp+1][1], acc[2*ntp+1][2], acc[2*ntp+1][3],
                         a0, zero, a2, zero, r2, r3);
            }
            #pragma unroll
            for (int ntp = 0; ntp < 2; ntp++){
                uint32_t r0, r1, r2, r3;
                ldsm_x4(r0, r1, r2, r3, bb2[ntp] + (uint32_t)(k0 * 2));
                mma16816(accp[2*ntp][0],   accp[2*ntp][1],   accp[2*ntp][2],   accp[2*ntp][3],
                         a0, zero, a2, zero, r0, r1);
                mma16816(accp[2*ntp+1][0], accp[2*ntp+1][1], accp[2*ntp+1][2], accp[2*ntp+1][3],
                         a0, zero, a2, zero, r2, r3);
            }
        }

        // ---- epi2: h2[t-1] (skip at t=0; h2[-1] buffer must stay zero) ----
        if (t > 0){
            #pragma unroll
            for (int nt = 0; nt < 2; nt++){
                float gi = accp[nt][0]     + acc2h[nt][0]     + bias2[nt].x;
                float gf = accp[nt][1]     + acc2h[nt][1]     + bias2[nt].y;
                float gg = accp[nt + 2][0] + acc2h[nt + 2][0] + bias2[nt + 2].x;
                float go = accp[nt + 2][1] + acc2h[nt + 2][1] + bias2[nt + 2].y;
                float c = siga(gf) * cst2[nt] + siga(gi) * tanha(gg);
                cst2[nt] = c;
                hw2[gp * 72 + (ubase2 + nt * 4)] = __float2half(siga(go) * tanha(c));
            }
        }

        // ---- epi1: h1[t] ----
        #pragma unroll
        for (int nt = 0; nt < 4; nt++){
            float2 xif = __half22float2(*(const __half2*)&xcur[nt]);
            float2 xgo = __half22float2(*(const __half2*)&xcur[nt + 4]);
            float gi = acc[nt][0]     + xif.x;
            float gf = acc[nt][1]     + xif.y;
            float gg = acc[nt + 4][0] + xgo.x;
            float go = acc[nt + 4][1] + xgo.y;
            float c = siga(gf) * cst1[nt] + siga(gi) * tanha(gg);
            cst1[nt] = c;
            hw1[gp * 136 + (ubase1 + nt * 4)] = __float2half(siga(go) * tanha(c));
        }
        #pragma unroll
        for (int nt = 0; nt < 8; nt++) xcur[nt] = xnxt[nt];
        __syncthreads();   // single barrier per step
    }

    // ---- tail: produce h2[511] from h1[511], h2[510] ----
    {
        const __half* hr1 = sH1 + 1 * 8 * 136;   // h1[511] (parity 1)
        const __half* hr2 = sH2 + 0 * 8 * 72;    // h2[510] (parity 0)
        __half*       hw2 = sH2 + 1 * 8 * 72;    // h2[511] (parity 1)

        float accp[4][4];
        #pragma unroll
        for (int nt = 0; nt < 4; nt++){
            accp[nt][0]=0.f; accp[nt][1]=0.f; accp[nt][2]=0.f; accp[nt][3]=0.f;
        }
        float acc2h[4][4];
        #pragma unroll
        for (int nt = 0; nt < 4; nt++){
            acc2h[nt][0]=0.f; acc2h[nt][1]=0.f; acc2h[nt][2]=0.f; acc2h[nt][3]=0.f;
        }

        #pragma unroll
        for (int k2t = 0; k2t < 4; k2t++){
            const int k0 = k2t * 16;
            const __half* ap = hr2 + gp * 72 + k0 + 2 * tig;
            uint32_t a0 = *(const uint32_t*)ap;
            uint32_t a2 = *(const uint32_t*)(ap + 8);
            #pragma unroll
            for (int p = 0; p < 2; p++){
                mma16816(acc2h[2*p][0],   acc2h[2*p][1],   acc2h[2*p][2],   acc2h[2*p][3],
                         a0, zero, a2, zero, fhh[k2t][p][0], fhh[k2t][p][1]);
                mma16816(acc2h[2*p+1][0], acc2h[2*p+1][1], acc2h[2*p+1][2], acc2h[2*p+1][3],
                         a0, zero, a2, zero, fhh[k2t][p][2], fhh[k2t][p][3]);
            }
        }
        #pragma unroll
        for (int kt = 0; kt < 8; kt++){
            const int k0 = kt * 16;
            const __half* ap = hr1 + gp * 136 + k0 + 2 * tig;
            uint32_t a0 = *(const uint32_t*)ap;
            uint32_t a2 = *(const uint32_t*)(ap + 8);
            #pragma unroll
            for (int ntp = 0; ntp < 2; ntp++){
                uint32_t r0, r1, r2, r3;
                ldsm_x4(r0, r1, r2, r3, bb2[ntp] + (uint32_t)(k0 * 2));
                mma16816(accp[2*ntp][0],   accp[2*ntp][1],   accp[2*ntp][2],   accp[2*ntp][3],
                         a0, zero, a2, zero, r0, r1);
                mma16816(accp[2*ntp+1][0], accp[2*ntp+1][1], accp[2*ntp+1][2], accp[2*ntp+1][3],
                         a0, zero, a2, zero, r2, r3);
            }
        }

        #pragma unroll
        for (int nt = 0; nt < 2; nt++){
            float gi = accp[nt][0]     + acc2h[nt][0]     + bias2[nt].x;
            float gf = accp[nt][1]     + acc2h[nt][1]     + bias2[nt].y;
            float gg = accp[nt + 2][0] + acc2h[nt + 2][0] + bias2[nt + 2].x;
            float go = accp[nt + 2][1] + acc2h[nt + 2][1] + bias2[nt + 2].y;
            float c = siga(gf) * cst2[nt] + siga(gi) * tanha(gg);
            cst2[nt] = c;
            hw2[gp * 72 + (ubase2 + nt * 4)] = __float2half(siga(go) * tanha(c));
        }
        __syncthreads();
    }

    // ---- fused FC head: h2[511] in sH2 buf 1 ----
    const __half* hf = sH2 + 8 * 72;
    const int m = w, r = lane;
    float s = (r < 32) ? fc1b[r] : 0.f;
    #pragma unroll 8
    for (int k = 0; k < 64; k++)
        s += __half2float(hf[m * 72 + k]) * fc1w[r * 64 + k];
    float z = fmaxf(s, 0.f) * fc2w[r];
    #pragma unroll
    for (int off = 16; off > 0; off >>= 1)
        z += __shfl_xor_sync(0xffffffffu, z, off);
    if (r == 0) out[b0 + m] = sigf(z + fc2b[0]);
}

// =====================================================================
extern "C" void kernel_launch(void* const* d_in, const int* in_sizes, int n_in,
                              void* d_out, int out_size)
{
    const float* X     = (const float*)d_in[0];
    const float* W1_ih = (const float*)d_in[1];
    const float* W1_hh = (const float*)d_in[2];
    const float* b1_ih = (const float*)d_in[3];
    const float* b1_hh = (const float*)d_in[4];
    const float* W2_ih = (const float*)d_in[5];
    const float* W2_hh = (const float*)d_in[6];
    const float* b2_ih = (const float*)d_in[7];
    const float* b2_hh = (const float*)d_in[8];
    const float* fc1w  = (const float*)d_in[9];
    const float* fc1b  = (const float*)d_in[10];
    const float* fc2w  = (const float*)d_in[11];
    const float* fc2b  = (const float*)d_in[12];
    float* out = (float*)d_out;

    const int g1_smem = 2 * 128 * 120 * 2;                           // 61440 B
    const int fu_smem = (768 * 136 + 2 * 8 * 136 + 2 * 8 * 72) * 2;  // 215552 B

    cudaFuncSetAttribute(gemm1_tc,     cudaFuncAttributeMaxDynamicSharedMemorySize, g1_smem);
    cudaFuncSetAttribute(fused_kernel, cudaFuncAttributeMaxDynamicSharedMemorySize, fu_smem);

    prep_kernel<<<128, 256>>>(W1_ih, W1_hh, b1_ih, b1_hh, W2_ih, W2_hh, b2_ih, b2_hh);
    gemm1_tc<<<dim3(4, 4096), 256, g1_smem>>>(X);
    fused_kernel<<<128, 256, fu_smem>>>(fc1w, fc1b, fc2w, fc2b, out);
}

// round 13
// speedup vs baseline: 1.8300x; 1.8300x over previous
#include <cuda_runtime.h>
#include <cuda_fp16.h>
#include <cstdint>

typedef unsigned long long ull;

// ---------------- scratch (static device allocations; no cudaMalloc) ----------------
__device__ __half g_xw1h[268435456];  // [T=512][B=1024][n=512] fp16  (512 MiB)

// preconverted weights (fp16) + combined biases (fp32)
// Gate-column mapping (layer 1): n = wq*64 + s, wq = j/16:
//   s = 2*(j%16) + q          q in {0,1}  (i,f pairs -> tiles 0..3 of warp)
//   s = 32 + 2*(j%16) + q-2   q in {2,3}  (g,o pairs -> tiles 4..7)
// Layer 2: 32-col blocks, 8 units each, analogous.
__device__ __half g_w1[512 * 112];    // W1_ih n-major: [n][k], k padded 100->112
__device__ __half g_w2[256 * 128];    // W2_ih n-major: [n][k=128]
__device__ __half g_w1hh[65536];      // W1_hh n-major: [n=512][k=128]
__device__ __half g_w2hh[16384];      // W2_hh n-major: [n=256][k=64]
__device__ float  g_b1[512];
__device__ float  g_b2[256];

// ---------------- helpers ----------------
__device__ __forceinline__ float sigf(float x){ return 1.f / (1.f + __expf(-x)); }
__device__ __forceinline__ float tanha(float x){
    float y; asm("tanh.approx.f32 %0, %1;" : "=f"(y) : "f"(x)); return y;
}
__device__ __forceinline__ float siga(float x){ return fmaf(0.5f, tanha(0.5f * x), 0.5f); }

__device__ __forceinline__ uint32_t smem_u32(const void* p){
    return (uint32_t)__cvta_generic_to_shared(p);
}

__device__ __forceinline__ void mma16816(float& c0, float& c1, float& c2, float& c3,
                                         uint32_t a0, uint32_t a1, uint32_t a2, uint32_t a3,
                                         uint32_t b0, uint32_t b1){
    asm("mma.sync.aligned.m16n8k16.row.col.f32.f16.f16.f32 "
        "{%0,%1,%2,%3}, {%4,%5,%6,%7}, {%8,%9}, {%0,%1,%2,%3};"
        : "+f"(c0), "+f"(c1), "+f"(c2), "+f"(c3)
        : "r"(a0), "r"(a1), "r"(a2), "r"(a3), "r"(b0), "r"(b1));
}

__device__ __forceinline__ void ldsm_x4(uint32_t& r0, uint32_t& r1, uint32_t& r2, uint32_t& r3,
                                        uint32_t addr){
    asm("ldmatrix.sync.aligned.m8n8.x4.shared.b16 {%0,%1,%2,%3}, [%4];"
        : "=r"(r0), "=r"(r1), "=r"(r2), "=r"(r3) : "r"(addr));
}

// gate mapping helpers (prep only) — layer1: 64-col blocks, layer2: 32-col blocks
__device__ __forceinline__ void n_to_gj1(int n, int& g, int& j){
    int wq = n >> 6, s = n & 63;
    int q;
    if (s < 32){ j = wq * 16 + (s >> 1); q = s & 1; }
    else        { int s2 = s - 32; j = wq * 16 + (s2 >> 1); q = 2 + (s2 & 1); }
    g = q * 128 + j;
}
__device__ __forceinline__ void n_to_gj2(int n, int& g, int& j){
    int wq = n >> 5, s = n & 31;
    int q;
    if (s < 16){ j = wq * 8 + (s >> 1); q = s & 1; }
    else        { int s2 = s - 16; j = wq * 8 + (s2 >> 1); q = 2 + (s2 & 1); }
    g = q * 64 + j;
}

// =====================================================================
// PREP: one-shot weight conversion with gate-pair column mapping
// =====================================================================
__global__ void __launch_bounds__(256) prep_kernel(
    const float* __restrict__ W1_ih, const float* __restrict__ W1_hh,
    const float* __restrict__ b1_ih, const float* __restrict__ b1_hh,
    const float* __restrict__ W2_ih, const float* __restrict__ W2_hh,
    const float* __restrict__ b2_ih, const float* __restrict__ b2_hh)
{
    const int tid = blockIdx.x * blockDim.x + threadIdx.x;
    const int stride = gridDim.x * blockDim.x;
    for (int i = tid; i < 512 * 112; i += stride){
        int n = i / 112, k = i - n * 112;
        int g, j; n_to_gj1(n, g, j);
        g_w1[i] = __float2half(k < 100 ? W1_ih[g * 100 + k] : 0.f);
    }
    for (int i = tid; i < 256 * 128; i += stride){
        int n = i >> 7, k = i & 127;
        int g, j; n_to_gj2(n, g, j);
        g_w2[i] = __float2half(W2_ih[g * 128 + k]);
    }
    for (int i = tid; i < 65536; i += stride){
        int n = i >> 7, k = i & 127;
        int g, j; n_to_gj1(n, g, j);
        g_w1hh[i] = __float2half(W1_hh[g * 128 + k]);
    }
    for (int i = tid; i < 16384; i += stride){
        int n = i >> 6, k = i & 63;
        int g, j; n_to_gj2(n, g, j);
        g_w2hh[i] = __float2half(W2_hh[g * 64 + k]);
    }
    for (int i = tid; i < 512; i += stride){
        int g, j; n_to_gj1(i, g, j);
        g_b1[i] = b1_ih[g] + b1_hh[g];
    }
    for (int i = tid; i < 256; i += stride){
        int g, j; n_to_gj2(i, g, j);
        g_b2[i] = b2_ih[g] + b2_hh[g];
    }
}

// =====================================================================
// GEMM1 v2: one CTA per 128-row stripe, loops over the 4 column blocks.
// A loaded/converted ONCE; dedicated staging region keeps sA intact.
// =====================================================================
__global__ void __launch_bounds__(256) gemm1_tc(const float* __restrict__ X)
{
    extern __shared__ __half sm[];
    __half* sA  = sm;                     // [128][120]
    __half* sB  = sm + 128 * 120;         // [128][120] n-major
    __half* stg = sm + 2 * 128 * 120;     // [128][136] epilogue staging
    const int tid = threadIdx.x;
    const int rb = blockIdx.x;
    const int r0 = rb * 128;

    // A fill once: 128 rows x 100 floats via float4
    const float4* X4 = (const float4*)(X + (size_t)r0 * 100);
    for (int idx = tid; idx < 3200; idx += 256){
        int row = idx / 25, c4 = idx - row * 25;
        float4 v = X4[row * 25 + c4];
        __half2 h0 = __floats2half2_rn(v.x, v.y);
        __half2 h1 = __floats2half2_rn(v.z, v.w);
        ull packed = ((ull)(*(uint32_t*)&h1) << 32) | (*(uint32_t*)&h0);
        *(ull*)(sA + row * 120 + c4 * 4) = packed;
    }
    for (int idx = tid; idx < 768; idx += 256){
        int row = idx / 6, e = (idx - row * 6) * 2;
        *(uint32_t*)(sA + row * 120 + 100 + e) = 0u;
    }

    const int w = tid >> 5, lane = tid & 31;
    const int wm = w >> 2, wn = w & 3;
    const int m0w = wm * 64, n0w = wn * 32;
    const int gp = lane >> 2, tig = lane & 3;

    for (int cb = 0; cb < 4; cb++){
        const int n0c = cb * 128;

        // B fill for this column block
        for (int idx = tid; idx < 1792; idx += 256){
            int nn = idx / 14, c8 = (idx - nn * 14) * 8;
            *(int4*)(sB + nn * 120 + c8) = *(const int4*)(g_w1 + (size_t)(n0c + nn) * 112 + c8);
        }
        __syncthreads();   // sA (first iter) + sB visible; prior stg reads done

        float acc[4][4][4];
        #pragma unroll
        for (int mt = 0; mt < 4; mt++)
            #pragma unroll
            for (int nt = 0; nt < 4; nt++){
                acc[mt][nt][0]=0.f; acc[mt][nt][1]=0.f; acc[mt][nt][2]=0.f; acc[mt][nt][3]=0.f;
            }

        float2 bias[4];
        #pragma unroll
        for (int nt = 0; nt < 4; nt++)
            bias[nt] = *(const float2*)(g_b1 + n0c + n0w + nt * 8 + 2 * tig);

        #pragma unroll
        for (int kt = 0; kt < 7; kt++){
            const int k0 = kt * 16;
            uint32_t af[4][4];
            #pragma unroll
            for (int mt = 0; mt < 4; mt++){
                const __half* ap = sA + (m0w + mt * 16 + gp) * 120 + k0 + 2 * tig;
                af[mt][0] = *(const uint32_t*)ap;
                af[mt][1] = *(const uint32_t*)(ap + 8 * 120);
                af[mt][2] = *(const uint32_t*)(ap + 8);
                af[mt][3] = *(const uint32_t*)(ap + 8 * 120 + 8);
            }
            #pragma unroll
            for (int nt = 0; nt < 4; nt++){
                const __half* bp = sB + (n0w + nt * 8 + gp) * 120 + k0 + 2 * tig;
                uint32_t b0 = *(const uint32_t*)bp;
                uint32_t b1 = *(const uint32_t*)(bp + 8);
                #pragma unroll
                for (int mt = 0; mt < 4; mt++)
                    mma16816(acc[mt][nt][0], acc[mt][nt][1], acc[mt][nt][2], acc[mt][nt][3],
                             af[mt][0], af[mt][1], af[mt][2], af[mt][3], b0, b1);
            }
        }

        // stage epilogue, then coalesced int4 stores
        #pragma unroll
        for (int mt = 0; mt < 4; mt++){
            int ra = m0w + mt * 16 + gp;
            #pragma unroll
            for (int nt = 0; nt < 4; nt++){
                int nl = n0w + nt * 8 + 2 * tig;
                __half2 v0 = __floats2half2_rn(acc[mt][nt][0] + bias[nt].x, acc[mt][nt][1] + bias[nt].y);
                __half2 v1 = __floats2half2_rn(acc[mt][nt][2] + bias[nt].x, acc[mt][nt][3] + bias[nt].y);
                *(__half2*)(stg + ra * 136 + nl) = v0;
                *(__half2*)(stg + (ra + 8) * 136 + nl) = v1;
            }
        }
        __syncthreads();   // stg writes done; sB reads done (safe to refill next iter)
        #pragma unroll
        for (int i = 0; i < 8; i++){
            int idx = tid + i * 256;
            int row = idx >> 4, col8 = (idx & 15) * 8;
            int r = r0 + row;
            size_t orow = (size_t)(r & 511) * 1024 + (r >> 9);
            *(int4*)(g_xw1h + orow * 512 + n0c + col8) = *(const int4*)(stg + row * 136 + col8);
        }
        // next iteration's post-B-fill __syncthreads covers these stg reads
    }
}

// =====================================================================
// FUSED v1 (reverted, proven 1365us total): rec1 + proj2 + rec2 + FC head.
// 128 CTAs x 8 batch rows, 8 warps. Two syncs per step.
// =====================================================================
__global__ void __launch_bounds__(256, 1) fused_kernel(
    const float* __restrict__ fc1w, const float* __restrict__ fc1b,
    const float* __restrict__ fc2w, const float* __restrict__ fc2b,
    float* __restrict__ out)
{
    extern __shared__ __half smf[];
    __half* sW1  = smf;                    // [512][136]
    __half* sW2i = smf + 512 * 136;        // [256][136]
    __half* sH1  = smf + 768 * 136;        // [2][8][136]
    __half* sH2  = sH1 + 2 * 8 * 136;      // [2][8][72]

    const int tid  = threadIdx.x;
    const int w    = tid >> 5;
    const int lane = tid & 31;
    const int gp   = lane >> 2;
    const int tig  = lane & 3;
    const int b0   = blockIdx.x * 8;

    // ---- init 1: stage W2hh [256][72] into sW1 region, build reg fragments ----
    for (int idx = tid; idx < 2048; idx += 256){
        int nn = idx >> 3, c8 = (idx & 7) * 8;
        *(int4*)(sW1 + nn * 72 + c8) = *(const int4*)(g_w2hh + nn * 64 + c8);
    }
    __syncthreads();

    uint32_t fhh[4][2][4];   // [k2t][pair][r0..r3]
    {
        int rowo = (lane & 7) + ((lane & 16) ? 8 : 0);
        int kcol = ((lane >> 3) & 1) * 8;
        uint32_t base = smem_u32(sW1);
        #pragma unroll
        for (int p = 0; p < 2; p++){
            uint32_t addr = base + (uint32_t)(((w * 32 + p * 16 + rowo) * 72 + kcol) * 2);
            #pragma unroll
            for (int k2t = 0; k2t < 4; k2t++)
                ldsm_x4(fhh[k2t][p][0], fhh[k2t][p][1], fhh[k2t][p][2], fhh[k2t][p][3],
                        addr + (uint32_t)(k2t * 32));
        }
    }
    __syncthreads();

    // ---- init 2: load W1hh, W2ih; zero h buffers ----
    for (int idx = tid; idx < 8192; idx += 256){
        int nn = idx >> 4, c8 = (idx & 15) * 8;
        *(int4*)(sW1 + nn * 136 + c8) = *(const int4*)(g_w1hh + nn * 128 + c8);
    }
    for (int idx = tid; idx < 4096; idx += 256){
        int nn = idx >> 4, c8 = (idx & 15) * 8;
        *(int4*)(sW2i + nn * 136 + c8) = *(const int4*)(g_w2 + nn * 128 + c8);
    }
    for (int i = tid; i < 1088; i += 256) ((uint32_t*)sH1)[i] = 0u;
    for (int i = tid; i < 576; i += 256)  ((uint32_t*)sH2)[i] = 0u;
    __syncthreads();

    // ldmatrix bases
    uint32_t bb1[4], bb2[2];
    {
        int rowo = (lane & 7) + ((lane & 16) ? 8 : 0);
        int kcol = ((lane >> 3) & 1) * 8;
        uint32_t w1base = smem_u32(sW1);
        #pragma unroll
        for (int ntp = 0; ntp < 4; ntp++)
            bb1[ntp] = w1base + (uint32_t)(((w * 64 + ntp * 16 + rowo) * 136 + kcol) * 2);
        uint32_t w2base = smem_u32(sW2i);
        #pragma unroll
        for (int ntp = 0; ntp < 2; ntp++)
            bb2[ntp] = w2base + (uint32_t)(((w * 32 + ntp * 16 + rowo) * 136 + kcol) * 2);
    }

    float cst1[4] = {0.f, 0.f, 0.f, 0.f};   // layer1 cells (units ubase1 + nt*4)
    float cst2[2] = {0.f, 0.f};             // layer2 cells
    const uint32_t zero = 0u;
    const int cA     = w * 64 + 2 * tig;
    const int ubase1 = w * 16 + tig;
    const int ubase2 = w * 8 + tig;

    float2 bias2[4];
    #pragma unroll
    for (int nt = 0; nt < 4; nt++)
        bias2[nt] = *(const float2*)(g_b2 + w * 32 + nt * 8 + 2 * tig);

    // preload xw1 for t=0
    uint32_t xcur[8], xnxt[8];
    {
        const __half* xb = g_xw1h + ((size_t)b0 + gp) * 512 + cA;
        #pragma unroll
        for (int nt = 0; nt < 8; nt++) xcur[nt] = *(const uint32_t*)(xb + nt * 8);
    }

    for (int t = 0; t < 512; t++){
        const __half* hr1 = sH1 + (1 - (t & 1)) * 8 * 136;
        __half*       hw1 = sH1 + (t & 1) * 8 * 136;
        const __half* hr2 = sH2 + (1 - (t & 1)) * 8 * 72;
        __half*       hw2 = sH2 + (t & 1) * 8 * 72;

        // prefetch xw1 for t+1
        {
            int tn = (t < 511) ? t + 1 : t;
            const __half* xb = g_xw1h + ((size_t)tn * 1024 + b0 + gp) * 512 + cA;
            #pragma unroll
            for (int nt = 0; nt < 8; nt++) xnxt[nt] = *(const uint32_t*)(xb + nt * 8);
        }

        // ---- phase A: rec2-hh MMA (h2[t-1]) + rec1 MMA (h1[t-1]) + epi1 ----
        float acc2h[4][4];
        #pragma unroll
        for (int nt = 0; nt < 4; nt++){
            acc2h[nt][0]=0.f; acc2h[nt][1]=0.f; acc2h[nt][2]=0.f; acc2h[nt][3]=0.f;
        }
        #pragma unroll
        for (int k2t = 0; k2t < 4; k2t++){
            const int k0 = k2t * 16;
            const __half* ap = hr2 + gp * 72 + k0 + 2 * tig;
            uint32_t a0 = *(const uint32_t*)ap;
            uint32_t a2 = *(const uint32_t*)(ap + 8);
            #pragma unroll
            for (int p = 0; p < 2; p++){
                mma16816(acc2h[2*p][0],   acc2h[2*p][1],   acc2h[2*p][2],   acc2h[2*p][3],
                         a0, zero, a2, zero, fhh[k2t][p][0], fhh[k2t][p][1]);
                mma16816(acc2h[2*p+1][0], acc2h[2*p+1][1], acc2h[2*p+1][2], acc2h[2*p+1][3],
                         a0, zero, a2, zero, fhh[k2t][p][2], fhh[k2t][p][3]);
            }
        }

        float acc[8][4];
        #pragma unroll
        for (int nt = 0; nt < 8; nt++){
            acc[nt][0]=0.f; acc[nt][1]=0.f; acc[nt][2]=0.f; acc[nt][3]=0.f;
        }
        #pragma unroll
        for (int kt = 0; kt < 8; kt++){
            const int k0 = kt * 16;
            const __half* ap = hr1 + gp * 136 + k0 + 2 * tig;
            uint32_t a0 = *(const uint32_t*)ap;
            uint32_t a2 = *(const uint32_t*)(ap + 8);
            #pragma unroll
            for (int ntp = 0; ntp < 4; ntp++){
                uint32_t r0, r1, r2, r3;
                ldsm_x4(r0, r1, r2, r3, bb1[ntp] + (uint32_t)(k0 * 2));
                mma16816(acc[2*ntp][0],   acc[2*ntp][1],   acc[2*ntp][2],   acc[2*ntp][3],
                         a0, zero, a2, zero, r0, r1);
                mma16816(acc[2*ntp+1][0], acc[2*ntp+1][1], acc[2*ntp+1][2], acc[2*ntp+1][3],
                         a0, zero, a2, zero, r2, r3);
            }
        }

        // epi1: nt has (i,f) of unit ubase1+nt*4; nt+4 has (g,o)
        #pragma unroll
        for (int nt = 0; nt < 4; nt++){
            float2 xif = __half22float2(*(const __half2*)&xcur[nt]);
            float2 xgo = __half22float2(*(const __half2*)&xcur[nt + 4]);
            float gi = acc[nt][0]     + xif.x;
            float gf = acc[nt][1]     + xif.y;
            float gg = acc[nt + 4][0] + xgo.x;
            float go = acc[nt + 4][1] + xgo.y;
            float c = siga(gf) * cst1[nt] + siga(gi) * tanha(gg);
            cst1[nt] = c;
            hw1[gp * 136 + (ubase1 + nt * 4)] = __float2half(siga(go) * tanha(c));
        }
        #pragma unroll
        for (int nt = 0; nt < 8; nt++) xcur[nt] = xnxt[nt];
        __syncthreads();   // h1[t] visible

        // ---- phase B: proj MMA (h1[t] @ W2ih) + epi2 ----
        float accp[4][4];
        #pragma unroll
        for (int nt = 0; nt < 4; nt++){
            accp[nt][0]=0.f; accp[nt][1]=0.f; accp[nt][2]=0.f; accp[nt][3]=0.f;
        }
        #pragma unroll
        for (int kt = 0; kt < 8; kt++){
            const int k0 = kt * 16;
            const __half* ap = hw1 + gp * 136 + k0 + 2 * tig;
            uint32_t a0 = *(const uint32_t*)ap;
            uint32_t a2 = *(const uint32_t*)(ap + 8);
            #pragma unroll
            for (int ntp = 0; ntp < 2; ntp++){
                uint32_t r0, r1, r2, r3;
                ldsm_x4(r0, r1, r2, r3, bb2[ntp] + (uint32_t)(k0 * 2));
                mma16816(accp[2*ntp][0],   accp[2*ntp][1],   accp[2*ntp][2],   accp[2*ntp][3],
                         a0, zero, a2, zero, r0, r1);
                mma16816(accp[2*ntp+1][0], accp[2*ntp+1][1], accp[2*ntp+1][2], accp[2*ntp+1][3],
                         a0, zero, a2, zero, r2, r3);
            }
        }

        // epi2: nt in {0,1} = (i,f) of unit ubase2+nt*4; nt+2 = (g,o)
        #pragma unroll
        for (int nt = 0; nt < 2; nt++){
            float gi = accp[nt][0]     + acc2h[nt][0]     + bias2[nt].x;
            float gf = accp[nt][1]     + acc2h[nt][1]     + bias2[nt].y;
            float gg = accp[nt + 2][0] + acc2h[nt + 2][0] + bias2[nt + 2].x;
            float go = accp[nt + 2][1] + acc2h[nt + 2][1] + bias2[nt + 2].y;
            float c = siga(gf) * cst2[nt] + siga(gi) * tanha(gg);
            cst2[nt] = c;
            hw2[gp * 72 + (ubase2 + nt * 4)] = __float2half(siga(go) * tanha(c));
        }
        __syncthreads();   // h2[t] visible for next step
    }

    // ---- fused FC head: final h2 in buf 1 (t=511 wrote sH2 + 8*72) ----
    const __half* hf = sH2 + 8 * 72;
    const int m = w, r = lane;
    float s = (r < 32) ? fc1b[r] : 0.f;
    #pragma unroll 8
    for (int k = 0; k < 64; k++)
        s += __half2float(hf[m * 72 + k]) * fc1w[r * 64 + k];
    float z = fmaxf(s, 0.f) * fc2w[r];
    #pragma unroll
    for (int off = 16; off > 0; off >>= 1)
        z += __shfl_xor_sync(0xffffffffu, z, off);
    if (r == 0) out[b0 + m] = sigf(z + fc2b[0]);
}

// =====================================================================
extern "C" void kernel_launch(void* const* d_in, const int* in_sizes, int n_in,
                              void* d_out, int out_size)
{
    const float* X     = (const float*)d_in[0];
    const float* W1_ih = (const float*)d_in[1];
    const float* W1_hh = (const float*)d_in[2];
    const float* b1_ih = (const float*)d_in[3];
    const float* b1_hh = (const float*)d_in[4];
    const float* W2_ih = (const float*)d_in[5];
    const float* W2_hh = (const float*)d_in[6];
    const float* b2_ih = (const float*)d_in[7];
    const float* b2_hh = (const float*)d_in[8];
    const float* fc1w  = (const float*)d_in[9];
    const float* fc1b  = (const float*)d_in[10];
    const float* fc2w  = (const float*)d_in[11];
    const float* fc2b  = (const float*)d_in[12];
    float* out = (float*)d_out;

    const int g1_smem = (2 * 128 * 120 + 128 * 136) * 2;             // 96256 B
    const int fu_smem = (768 * 136 + 2 * 8 * 136 + 2 * 8 * 72) * 2;  // 215552 B

    cudaFuncSetAttribute(gemm1_tc,     cudaFuncAttributeMaxDynamicSharedMemorySize, g1_smem);
    cudaFuncSetAttribute(fused_kernel, cudaFuncAttributeMaxDynamicSharedMemorySize, fu_smem);

    prep_kernel<<<128, 256>>>(W1_ih, W1_hh, b1_ih, b1_hh, W2_ih, W2_hh, b2_ih, b2_hh);
    gemm1_tc<<<4096, 256, g1_smem>>>(X);
    fused_kernel<<<128, 256, fu_smem>>>(fc1w, fc1b, fc2w, fc2b, out);
}